// round 7
// baseline (speedup 1.0000x reference)
#include <cuda_runtime.h>

#define VOCAB 9
#define D     4
#define S     16384

#define NBLK  16
#define NTHR  256   // 8 warps; 16*256 = 4096 threads, 4 output rows each

// Packed shared weight layout (121 floats):
//   [0,36)    emb      (9x4)
//   [36,52)   proj_w   (4x4)
//   [52,56)   proj_b   (4)
//   [56,72)   forw_w   (4x4)
//   [72,76)   forw_b   (4)
//   [76,112)  prj_w    (9x4)
//   [112,121) prj_b    (9)
#define W_EMB   0
#define W_PROJW 36
#define W_PROJB 52
#define W_FORWW 56
#define W_FORWB 72
#define W_PRJW  76
#define W_PRJB  112
#define W_TOTAL 121

// ---------------------------------------------------------------------------
// Single fused kernel; critical path = one (int32) or two (int64) exposed
// global latencies, everything else overlapped.
//  Entry:   threads 0..120 prefetch ALL weight floats (1 LDG each) -> shared,
//           concurrently with the 16-int4/thread speculative token batch.
//  Phase A: batch1 = int4 indices [0,4096) (valid under both layouts).
//           Detection = block consensus (int64 LE <=> .y/.w zero, .x/.z < 9).
//           Count .x/.z of batch1 BEFORE the barrier (needed either way).
//           int64: reuse v[] for batch2 (tokens 8192..16383), plus 2 early
//           payload loads. int32: count .y/.w, payload = v[bid].
//           Histogram = ONE packed uint64/thread (9 counters x 7 bits).
//  Phase B: h0 from shared weights; 9-thread table pipeline -> sp[81].
//  Phase C: scatter — 4 rows/thread = 9 aligned float4 stores.
// ---------------------------------------------------------------------------
__global__ void __launch_bounds__(NTHR) bert_fused_kernel(
    const int* __restrict__ x32,
    const float* __restrict__ emb,
    const float* __restrict__ proj_w,
    const float* __restrict__ proj_b,
    const float* __restrict__ forw_w,
    const float* __restrict__ forw_b,
    const float* __restrict__ prj_w,
    const float* __restrict__ prj_b,
    float4* __restrict__ out4)
{
    __shared__ int   s_ok[8];
    __shared__ int   warp_cnt[8][VOCAB];
    __shared__ float sw[W_TOTAL];
    __shared__ float h0s[VOCAB][D];
    __shared__ float sp[VOCAB * VOCAB];

    const int tid  = threadIdx.x;
    const int wid  = tid >> 5;
    const int lane = tid & 31;
    const int bid  = blockIdx.x;
    const int4* p4 = (const int4*)x32;

    // ---- weight prefetch: one LDG per thread, issued first ----
    float wreg = 0.f;
    if (tid < W_TOTAL) {
        const float* src;
        int q = tid;
        if      (q < W_PROJW) src = emb     + (q - W_EMB);
        else if (q < W_PROJB) src = proj_w  + (q - W_PROJW);
        else if (q < W_FORWW) src = proj_b  + (q - W_PROJB);
        else if (q < W_FORWB) src = forw_w  + (q - W_FORWW);
        else if (q < W_PRJW)  src = forw_b  + (q - W_FORWB);
        else if (q < W_PRJB)  src = prj_w   + (q - W_PRJW);
        else                  src = prj_b   + (q - W_PRJB);
        wreg = __ldg(src);
    }

    // ---- batch1: speculative int32-interp loads (in-bounds both ways) ----
    int4 v[16];
    #pragma unroll
    for (int j = 0; j < 16; j++)
        v[j] = __ldg(p4 + tid + 256 * j);

    // ---- layout consensus on batch1 ----
    bool okb = true;
    #pragma unroll
    for (int j = 0; j < 16; j++)
        okb = okb && (v[j].y == 0) && (v[j].w == 0)
                  && ((unsigned)v[j].x < VOCAB) && ((unsigned)v[j].z < VOCAB);
    unsigned wall = __all_sync(0xffffffffu, okb);
    if (lane == 0) s_ok[wid] = (int)(wall != 0);

    // ---- count .x/.z (correct under BOTH layouts) while waiting ----
    unsigned long long acc = 0ULL;
    #pragma unroll
    for (int j = 0; j < 16; j++) {
        acc += 1ULL << (7 * v[j].x);
        acc += 1ULL << (7 * v[j].z);
    }

    if (tid < W_TOTAL) sw[tid] = wreg;
    __syncthreads();                              // #1: s_ok, sw visible

    int is64 = 1;
    #pragma unroll
    for (int w = 0; w < 8; w++) is64 &= s_ok[w];

    int  vals[4];
    int4 pl0, pl1;                                // int64 scatter payload
    const int t = bid * NTHR + tid;               // this thread's row group

    if (is64) {
        // early payload loads (consumed only after barrier #3 — hidden)
        pl0 = __ldg(p4 + 2 * t);
        pl1 = __ldg(p4 + 2 * t + 1);
        // batch2: tokens 8192..16383, reuse v[] (no extra registers)
        #pragma unroll
        for (int j = 0; j < 16; j++)
            v[j] = __ldg(p4 + 4096 + tid + 256 * j);
    } else {
        // int32: .y/.w are real tokens too; payload already in v[bid]
        #pragma unroll
        for (int j = 0; j < 16; j++) {
            acc += 1ULL << (7 * v[j].y);
            acc += 1ULL << (7 * v[j].w);
        }
        vals[0] = v[bid].x; vals[1] = v[bid].y;
        vals[2] = v[bid].z; vals[3] = v[bid].w;
    }

    // ---- h0 from shared weights (threads 32..67; overlaps batch2 wait) ----
    if (tid >= 32 && tid < 32 + VOCAB * D) {
        int q = tid - 32;
        int vv = q / D, d = q % D;
        float a = sw[W_PROJB + d];
        #pragma unroll
        for (int k = 0; k < D; k++)
            a += sw[W_EMB + vv * D + k] * sw[W_PROJW + d * D + k];
        h0s[vv][d] = a;
    }

    if (is64) {
        #pragma unroll
        for (int j = 0; j < 16; j++) {
            acc += 1ULL << (7 * v[j].x);
            acc += 1ULL << (7 * v[j].z);
        }
    }

    // ---- reduce: unpack 9 counters, warp REDUX -> warp_cnt ----
    #pragma unroll
    for (int q = 0; q < VOCAB; q++) {
        unsigned c  = (unsigned)((acc >> (7 * q)) & 127ULL);
        unsigned ws = __reduce_add_sync(0xffffffffu, c);
        if (lane == 0) warp_cnt[wid][q] = (int)ws;
    }
    __syncthreads();                              // #2: warp_cnt, h0s visible

    // ---- per-distinct-row pipeline (9 threads) ----
    if (tid < VOCAB) {
        const int vv = tid;
        float hv0 = h0s[vv][0], hv1 = h0s[vv][1],
              hv2 = h0s[vv][2], hv3 = h0s[vv][3];

        float sc[VOCAB];
        float m = -3.4e38f;
        #pragma unroll
        for (int u = 0; u < VOCAB; u++) {
            float s = hv0 * h0s[u][0] + hv1 * h0s[u][1]
                    + hv2 * h0s[u][2] + hv3 * h0s[u][3];
            sc[u] = s;
            m = fmaxf(m, s);
        }

        // grouped softmax-weighted sum: attn @ h (exact regrouping by token)
        float wsum = 0.f, a0 = 0.f, a1 = 0.f, a2 = 0.f, a3 = 0.f;
        #pragma unroll
        for (int u = 0; u < VOCAB; u++) {
            int cu = 0;
            #pragma unroll
            for (int w = 0; w < 8; w++) cu += warp_cnt[w][u];
            float e = expf(sc[u] - m) * (float)cu;
            wsum += e;
            a0 += e * h0s[u][0];
            a1 += e * h0s[u][1];
            a2 += e * h0s[u][2];
            a3 += e * h0s[u][3];
        }
        float inv = 1.0f / wsum;
        float r0 = fmaxf(0.f, a0 * inv), r1 = fmaxf(0.f, a1 * inv);
        float r2 = fmaxf(0.f, a2 * inv), r3 = fmaxf(0.f, a3 * inv);

        // h2 = r @ forw_w.T + forw_b
        float h2[D];
        #pragma unroll
        for (int d = 0; d < D; d++) {
            h2[d] = sw[W_FORWB + d]
                  + sw[W_FORWW + d * D + 0] * r0
                  + sw[W_FORWW + d * D + 1] * r1
                  + sw[W_FORWW + d * D + 2] * r2
                  + sw[W_FORWW + d * D + 3] * r3;
        }

        // logits = h2 @ prj_w.T + prj_b ; softmax over VOCAB
        float lg[VOCAB];
        float m2 = -3.4e38f;
        #pragma unroll
        for (int c = 0; c < VOCAB; c++) {
            float a = sw[W_PRJB + c];
            #pragma unroll
            for (int k = 0; k < D; k++)
                a += sw[W_PRJW + c * D + k] * h2[k];
            lg[c] = a;
            m2 = fmaxf(m2, a);
        }
        float zsum = 0.f;
        #pragma unroll
        for (int c = 0; c < VOCAB; c++) {
            lg[c] = expf(lg[c] - m2);
            zsum += lg[c];
        }
        float zinv = 1.0f / zsum;
        #pragma unroll
        for (int c = 0; c < VOCAB; c++)
            sp[vv * VOCAB + c] = lg[c] * zinv;
    }
    __syncthreads();                              // #3: sp visible

    if (is64) {
        vals[0] = pl0.x; vals[1] = pl0.z;
        vals[2] = pl1.x; vals[3] = pl1.z;
    }

    // ---- scatter: thread t owns output rows 4t .. 4t+3 ----
    float4* o = out4 + (size_t)t * 9;
    #pragma unroll
    for (int k = 0; k < 9; k++) {
        float4 f;
        f.x = sp[vals[(4 * k + 0) / 9] * VOCAB + (4 * k + 0) % 9];
        f.y = sp[vals[(4 * k + 1) / 9] * VOCAB + (4 * k + 1) % 9];
        f.z = sp[vals[(4 * k + 2) / 9] * VOCAB + (4 * k + 2) % 9];
        f.w = sp[vals[(4 * k + 3) / 9] * VOCAB + (4 * k + 3) % 9];
        o[k] = f;
    }
}

extern "C" void kernel_launch(void* const* d_in, const int* in_sizes, int n_in,
                              void* d_out, int out_size)
{
    const int*   x      = (const int*)d_in[0];
    const float* emb    = (const float*)d_in[1];
    const float* proj_w = (const float*)d_in[2];
    const float* proj_b = (const float*)d_in[3];
    const float* forw_w = (const float*)d_in[4];
    const float* forw_b = (const float*)d_in[5];
    const float* prj_w  = (const float*)d_in[6];
    const float* prj_b  = (const float*)d_in[7];
    float* out = (float*)d_out;

    bert_fused_kernel<<<NBLK, NTHR>>>(x, emb, proj_w, proj_b,
                                      forw_w, forw_b, prj_w, prj_b,
                                      (float4*)out);
    (void)in_sizes; (void)n_in; (void)out_size;
}

// round 8
// speedup vs baseline: 1.1726x; 1.1726x over previous
#include <cuda_runtime.h>

#define VOCAB 9
#define D     4
#define S     16384

#define NBLK  16
#define NTHR  256   // 8 warps; 16*256 = 4096 threads, 4 output rows each

// Packed shared weight layout (121 floats):
#define W_EMB   0
#define W_PROJW 36
#define W_PROJB 52
#define W_FORWW 56
#define W_FORWB 72
#define W_PRJW  76
#define W_PRJB  112
#define W_TOTAL 121

// Cross-block scratch (zero-initialized at load; reset by last block each run
// so graph replays always start from zero).
__device__ int      g_cnt[VOCAB];
__device__ unsigned g_arrive;
__device__ unsigned g_done;

// ---------------------------------------------------------------------------
// Single kernel, DISTRIBUTED histogram (no redundant 128KB sweep per block).
//  probe  = p4[bid*256+tid]: detection sample + histogram slice + (int32)
//           scatter payload. int64 adds upper-half slice + payload (1 more
//           concurrent latency). Counts -> packed u64 -> REDUX -> 9 global
//           atomicAdds + arrive counter; spin until all 16 blocks posted
//           (co-resident => safe). Count-independent table math overlaps the
//           spin. Table computed redundantly per block; scatter 4 rows/thread.
// ---------------------------------------------------------------------------
__global__ void __launch_bounds__(NTHR) bert_fused_kernel(
    const int* __restrict__ x32,
    const float* __restrict__ emb,
    const float* __restrict__ proj_w,
    const float* __restrict__ proj_b,
    const float* __restrict__ forw_w,
    const float* __restrict__ forw_b,
    const float* __restrict__ prj_w,
    const float* __restrict__ prj_b,
    float4* __restrict__ out4)
{
    __shared__ int   s_ok[8];
    __shared__ int   warp_cnt[8][VOCAB];
    __shared__ float sw[W_TOTAL];
    __shared__ float h0s[VOCAB][D];
    __shared__ float sp[VOCAB * VOCAB];
    __shared__ float chk_sink;          // consumes atomic returns (never read)

    const int tid  = threadIdx.x;
    const int wid  = tid >> 5;
    const int lane = tid & 31;
    const int bid  = blockIdx.x;
    const int4* p4 = (const int4*)x32;
    const int pidx = bid * NTHR + tid;  // int4 probe index, < 4096 (in-bounds
                                        // under BOTH layouts); also scatter t.

    // ---- weight prefetch: one LDG per thread, issued first ----
    float wreg = 0.f;
    if (tid < W_TOTAL) {
        const float* src;
        int q = tid;
        if      (q < W_PROJW) src = emb     + (q - W_EMB);
        else if (q < W_PROJB) src = proj_w  + (q - W_PROJW);
        else if (q < W_FORWW) src = proj_b  + (q - W_PROJB);
        else if (q < W_FORWB) src = forw_w  + (q - W_FORWW);
        else if (q < W_PRJW)  src = forw_b  + (q - W_FORWB);
        else if (q < W_PRJB)  src = prj_w   + (q - W_PRJW);
        else                  src = prj_b   + (q - W_PRJB);
        wreg = __ldg(src);
    }

    // ---- probe load (1 int4/thread) ----
    int4 pr = __ldg(p4 + pidx);

    // detection consensus over this block's 256 int4 (512 odd words)
    bool okb = (pr.y == 0) && (pr.w == 0)
            && ((unsigned)pr.x < VOCAB) && ((unsigned)pr.z < VOCAB);
    unsigned wall = __all_sync(0xffffffffu, okb);
    if (lane == 0) s_ok[wid] = (int)(wall != 0);

    // count .x/.z (correct under both layouts); packed 9x7-bit counters
    unsigned long long acc = (1ULL << (7 * pr.x)) + (1ULL << (7 * pr.z));

    if (tid < W_TOTAL) sw[tid] = wreg;
    __syncthreads();                              // B1: s_ok, sw

    int is64 = 1;
    #pragma unroll
    for (int w = 0; w < 8; w++) is64 &= s_ok[w];

    int vals[4];
    if (is64) {
        // upper-half slice + scatter payload: 3 concurrent int4 loads
        int4 up  = __ldg(p4 + 4096 + pidx);       // tokens 8192+2*pidx, +1
        int4 pl0 = __ldg(p4 + 2 * pidx);          // tokens 4t, 4t+1
        int4 pl1 = __ldg(p4 + 2 * pidx + 1);      // tokens 4t+2, 4t+3
        acc += (1ULL << (7 * up.x)) + (1ULL << (7 * up.z));
        vals[0] = pl0.x; vals[1] = pl0.z; vals[2] = pl1.x; vals[3] = pl1.z;
    } else {
        acc += (1ULL << (7 * pr.y)) + (1ULL << (7 * pr.w));
        vals[0] = pr.x; vals[1] = pr.y; vals[2] = pr.z; vals[3] = pr.w;
    }

    // ---- per-warp reduce of packed counters ----
    #pragma unroll
    for (int q = 0; q < VOCAB; q++) {
        unsigned c  = (unsigned)((acc >> (7 * q)) & 127ULL);
        unsigned ws = __reduce_add_sync(0xffffffffu, c);
        if (lane == 0) warp_cnt[wid][q] = (int)ws;
    }

    // ---- h0 from shared weights (warp 1/2; independent of counts) ----
    if (tid >= 32 && tid < 32 + VOCAB * D) {
        int q = tid - 32;
        int vv = q / D, d = q % D;
        float a = sw[W_PROJB + d];
        #pragma unroll
        for (int k = 0; k < D; k++)
            a += sw[W_EMB + vv * D + k] * sw[W_PROJW + d * D + k];
        h0s[vv][d] = a;
    }
    __syncthreads();                              // B2: warp_cnt, h0s

    // ---- post block counts to global atomics ASAP (warp 0) ----
    if (wid == 0) {
        if (lane < VOCAB) {
            int bc = 0;
            #pragma unroll
            for (int w = 0; w < 8; w++) bc += warp_cnt[w][lane];
            int r = atomicAdd(&g_cnt[lane], bc);  // returned => completed @L2
            if (r == 0x5A5A5A5A) chk_sink = 1.f;  // impossible; keeps ATOM
        }
        __syncwarp();                             // all 9 adds visible
        if (lane == 0) {
            __threadfence();
            unsigned r2 = atomicAdd(&g_arrive, 1u);
            if (r2 == 0xFFFFFFFFu) chk_sink = 2.f;
        }
    }

    // ---- count-independent table precompute (overlaps other blocks) ----
    float eu[VOCAB];
    if (tid < VOCAB) {
        float hv0 = h0s[tid][0], hv1 = h0s[tid][1],
              hv2 = h0s[tid][2], hv3 = h0s[tid][3];
        float sc[VOCAB];
        float m = -3.4e38f;
        #pragma unroll
        for (int u = 0; u < VOCAB; u++) {
            float s = hv0 * h0s[u][0] + hv1 * h0s[u][1]
                    + hv2 * h0s[u][2] + hv3 * h0s[u][3];
            sc[u] = s;
            m = fmaxf(m, s);
        }
        #pragma unroll
        for (int u = 0; u < VOCAB; u++)
            eu[u] = __expf(sc[u] - m);
    }

    // ---- spin until all blocks posted counts (co-resident => safe) ----
    if (tid == 0) {
        volatile unsigned* pa = &g_arrive;
        while (*pa < (unsigned)NBLK) { }
    }
    __syncthreads();                              // B3: counts final

    // ---- finish table (9 threads) ----
    if (tid < VOCAB) {
        volatile int* pc = g_cnt;
        int cu[VOCAB];
        #pragma unroll
        for (int u = 0; u < VOCAB; u++) cu[u] = pc[u];

        float wsum = 0.f, a0 = 0.f, a1 = 0.f, a2 = 0.f, a3 = 0.f;
        #pragma unroll
        for (int u = 0; u < VOCAB; u++) {
            float e = eu[u] * (float)cu[u];
            wsum += e;
            a0 += e * h0s[u][0];
            a1 += e * h0s[u][1];
            a2 += e * h0s[u][2];
            a3 += e * h0s[u][3];
        }
        float inv = 1.0f / wsum;
        float r0 = fmaxf(0.f, a0 * inv), r1 = fmaxf(0.f, a1 * inv);
        float r2 = fmaxf(0.f, a2 * inv), r3 = fmaxf(0.f, a3 * inv);

        float h2[D];
        #pragma unroll
        for (int d = 0; d < D; d++) {
            h2[d] = sw[W_FORWB + d]
                  + sw[W_FORWW + d * D + 0] * r0
                  + sw[W_FORWW + d * D + 1] * r1
                  + sw[W_FORWW + d * D + 2] * r2
                  + sw[W_FORWW + d * D + 3] * r3;
        }

        float lg[VOCAB];
        float m2 = -3.4e38f;
        #pragma unroll
        for (int c = 0; c < VOCAB; c++) {
            float a = sw[W_PRJB + c];
            #pragma unroll
            for (int k = 0; k < D; k++)
                a += sw[W_PRJW + c * D + k] * h2[k];
            lg[c] = a;
            m2 = fmaxf(m2, a);
        }
        float zsum = 0.f;
        #pragma unroll
        for (int c = 0; c < VOCAB; c++) {
            lg[c] = __expf(lg[c] - m2);
            zsum += lg[c];
        }
        float zinv = 1.0f / zsum;
        #pragma unroll
        for (int c = 0; c < VOCAB; c++)
            sp[tid * VOCAB + c] = lg[c] * zinv;
    }
    __syncthreads();                              // B4: sp visible

    // ---- scatter: thread owns output rows 4*pidx .. 4*pidx+3 ----
    float4* o = out4 + (size_t)pidx * 9;
    #pragma unroll
    for (int k = 0; k < 9; k++) {
        float4 f;
        f.x = sp[vals[(4 * k + 0) / 9] * VOCAB + (4 * k + 0) % 9];
        f.y = sp[vals[(4 * k + 1) / 9] * VOCAB + (4 * k + 1) % 9];
        f.z = sp[vals[(4 * k + 2) / 9] * VOCAB + (4 * k + 2) % 9];
        f.w = sp[vals[(4 * k + 3) / 9] * VOCAB + (4 * k + 3) % 9];
        o[k] = f;
    }

    // ---- replay-safe reset: last finishing block zeroes the globals.
    //      r==NBLK-1 => every block passed B4 (all g_cnt reads done). ----
    if (tid == 0) {
        unsigned r = atomicAdd(&g_done, 1u);
        if (r == (unsigned)(NBLK - 1)) {
            #pragma unroll
            for (int q = 0; q < VOCAB; q++) g_cnt[q] = 0;
            g_arrive = 0u;
            __threadfence();
            g_done = 0u;
        }
    }
}

extern "C" void kernel_launch(void* const* d_in, const int* in_sizes, int n_in,
                              void* d_out, int out_size)
{
    const int*   x      = (const int*)d_in[0];
    const float* emb    = (const float*)d_in[1];
    const float* proj_w = (const float*)d_in[2];
    const float* proj_b = (const float*)d_in[3];
    const float* forw_w = (const float*)d_in[4];
    const float* forw_b = (const float*)d_in[5];
    const float* prj_w  = (const float*)d_in[6];
    const float* prj_b  = (const float*)d_in[7];
    float* out = (float*)d_out;

    bert_fused_kernel<<<NBLK, NTHR>>>(x, emb, proj_w, proj_b,
                                      forw_w, forw_b, prj_w, prj_b,
                                      (float4*)out);
    (void)in_sizes; (void)n_in; (void)out_size;
}

// round 12
// speedup vs baseline: 1.3090x; 1.1163x over previous
#include <cuda_runtime.h>

#define VOCAB 9
#define D     4
#define S     16384

#define NBLK  64
#define NTHR  64    // 2 warps; 64*64 = 4096 threads, 4 output rows each

// Packed shared weight layout (121 floats):
#define W_EMB   0
#define W_PROJW 36
#define W_PROJB 52
#define W_FORWW 56
#define W_FORWB 72
#define W_PRJW  76
#define W_PRJB  112
#define W_TOTAL 121

// Cross-block scratch (zero at load; last finishing block resets each run).
__device__ int      g_cnt[VOCAB];
__device__ unsigned g_arrive;
__device__ unsigned g_done;

// ---------------------------------------------------------------------------
// Distributed histogram + wide scatter.
//  64 blocks x 64 threads. Thread t = bid*64+tid probes p4[t] (whole array
//  under int32; lower-half tokens under int64). int64 adds upper-slice +
//  2 payload int4 (concurrent). Counts -> packed u64 -> REDUX -> posted to
//  global atomics IMMEDIATELY; h0/exp table math overlaps the arrive spin.
//  Each block finishes the 9x9 prob table redundantly; thread t scatters
//  rows 4t..4t+3 (9 aligned float4). Per-SM store tail ~4x smaller than R8.
// ---------------------------------------------------------------------------
__global__ void __launch_bounds__(NTHR) bert_fused_kernel(
    const int* __restrict__ x32,
    const float* __restrict__ emb,
    const float* __restrict__ proj_w,
    const float* __restrict__ proj_b,
    const float* __restrict__ forw_w,
    const float* __restrict__ forw_b,
    const float* __restrict__ prj_w,
    const float* __restrict__ prj_b,
    float4* __restrict__ out4)
{
    __shared__ int   s_ok[2];
    __shared__ int   warp_cnt[2][VOCAB];
    __shared__ float sw[W_TOTAL + 7];   // +pad
    __shared__ float h0s[VOCAB][D];
    __shared__ float sp[VOCAB * VOCAB];
    __shared__ float chk_sink;          // consumes atomic returns (never read)

    const int tid  = threadIdx.x;
    const int wid  = tid >> 5;          // 0 or 1
    const int lane = tid & 31;
    const int bid  = blockIdx.x;
    const int4* p4 = (const int4*)x32;
    const int t    = bid * NTHR + tid;  // probe index AND row-group id, <4096

    // ---- weight prefetch: 2 LDG per thread, issued first ----
    float wr0 = 0.f, wr1 = 0.f;
    {
        const float* srcs[2]; int n = 0;
        #pragma unroll
        for (int k = 0; k < 2; k++) {
            int q = tid + 64 * k;
            if (q < W_TOTAL) {
                const float* s;
                if      (q < W_PROJW) s = emb    + (q - W_EMB);
                else if (q < W_PROJB) s = proj_w + (q - W_PROJW);
                else if (q < W_FORWW) s = proj_b + (q - W_PROJB);
                else if (q < W_FORWB) s = forw_w + (q - W_FORWW);
                else if (q < W_PRJW)  s = forw_b + (q - W_FORWB);
                else if (q < W_PRJB)  s = prj_w  + (q - W_PRJW);
                else                  s = prj_b  + (q - W_PRJB);
                srcs[n++] = s;
            }
        }
        if (n > 0) wr0 = __ldg(srcs[0]);
        if (n > 1) wr1 = __ldg(srcs[1]);
    }

    // ---- probe load (1 int4/thread) ----
    int4 pr = __ldg(p4 + t);

    // detection consensus: int64 LE <=> odd words 0, even words < 9
    bool okb = (pr.y == 0) && (pr.w == 0)
            && ((unsigned)pr.x < VOCAB) && ((unsigned)pr.z < VOCAB);
    unsigned wall = __all_sync(0xffffffffu, okb);
    if (lane == 0) s_ok[wid] = (int)(wall != 0);

    // count .x/.z (correct under both layouts); packed 9x7-bit counters
    unsigned long long acc = (1ULL << (7 * pr.x)) + (1ULL << (7 * pr.z));

    if (tid < W_TOTAL)      sw[tid]      = wr0;
    if (tid + 64 < W_TOTAL) sw[tid + 64] = wr1;
    __syncthreads();                              // B1: s_ok, sw

    const int is64 = s_ok[0] & s_ok[1];

    int vals[4];
    if (is64) {
        int4 up  = __ldg(p4 + 4096 + t);          // tokens 8192+2t, 8193+2t
        int4 pl0 = __ldg(p4 + 2 * t);             // tokens 4t, 4t+1
        int4 pl1 = __ldg(p4 + 2 * t + 1);         // tokens 4t+2, 4t+3
        acc += (1ULL << (7 * up.x)) + (1ULL << (7 * up.z));
        vals[0] = pl0.x; vals[1] = pl0.z; vals[2] = pl1.x; vals[3] = pl1.z;
    } else {
        acc += (1ULL << (7 * pr.y)) + (1ULL << (7 * pr.w));
        vals[0] = pr.x; vals[1] = pr.y; vals[2] = pr.z; vals[3] = pr.w;
    }

    // ---- per-warp reduce of packed counters ----
    #pragma unroll
    for (int q = 0; q < VOCAB; q++) {
        unsigned c  = (unsigned)((acc >> (7 * q)) & 127ULL);
        unsigned ws = __reduce_add_sync(0xffffffffu, c);
        if (lane == 0) warp_cnt[wid][q] = (int)ws;
    }
    __syncthreads();                              // B2: warp_cnt

    // ---- post block counts IMMEDIATELY (warp 0) ----
    if (wid == 0) {
        if (lane < VOCAB) {
            int bc = warp_cnt[0][lane] + warp_cnt[1][lane];
            int r = atomicAdd(&g_cnt[lane], bc);  // returned => visible @L2
            if (r == 0x5A5A5A5A) chk_sink = 1.f;  // impossible; keeps ATOM
        }
        __syncwarp();
        if (lane == 0) {
            __threadfence();
            unsigned r2 = atomicAdd(&g_arrive, 1u);
            if (r2 == 0xFFFFFFFFu) chk_sink = 2.f;
        }
    }

    // ---- count-independent math overlaps other blocks' posting ----
    // h0[v][d] = emb[v]·proj_w[d] + proj_b[d]  (threads 0..35)
    if (tid < VOCAB * D) {
        int vv = tid / D, d = tid % D;
        float a = sw[W_PROJB + d];
        #pragma unroll
        for (int k = 0; k < D; k++)
            a += sw[W_EMB + vv * D + k] * sw[W_PROJW + d * D + k];
        h0s[vv][d] = a;
    }
    __syncthreads();                              // B2b: h0s

    float eu[VOCAB];
    if (tid < VOCAB) {
        float hv0 = h0s[tid][0], hv1 = h0s[tid][1],
              hv2 = h0s[tid][2], hv3 = h0s[tid][3];
        float sc[VOCAB];
        float m = -3.4e38f;
        #pragma unroll
        for (int u = 0; u < VOCAB; u++) {
            float s = hv0 * h0s[u][0] + hv1 * h0s[u][1]
                    + hv2 * h0s[u][2] + hv3 * h0s[u][3];
            sc[u] = s;
            m = fmaxf(m, s);
        }
        #pragma unroll
        for (int u = 0; u < VOCAB; u++)
            eu[u] = __expf(sc[u] - m);
    }

    // ---- spin until all 64 blocks posted (co-resident => safe) ----
    if (tid == 0) {
        volatile unsigned* pa = &g_arrive;
        while (*pa < (unsigned)NBLK) { }
    }
    __syncthreads();                              // B3: counts final

    // ---- finish table (9 threads) ----
    if (tid < VOCAB) {
        volatile int* pc = g_cnt;
        int cu[VOCAB];
        #pragma unroll
        for (int u = 0; u < VOCAB; u++) cu[u] = pc[u];

        float wsum = 0.f, a0 = 0.f, a1 = 0.f, a2 = 0.f, a3 = 0.f;
        #pragma unroll
        for (int u = 0; u < VOCAB; u++) {
            float e = eu[u] * (float)cu[u];
            wsum += e;
            a0 += e * h0s[u][0];
            a1 += e * h0s[u][1];
            a2 += e * h0s[u][2];
            a3 += e * h0s[u][3];
        }
        float inv = 1.0f / wsum;
        float r0 = fmaxf(0.f, a0 * inv), r1 = fmaxf(0.f, a1 * inv);
        float r2 = fmaxf(0.f, a2 * inv), r3 = fmaxf(0.f, a3 * inv);

        float h2[D];
        #pragma unroll
        for (int d = 0; d < D; d++) {
            h2[d] = sw[W_FORWB + d]
                  + sw[W_FORWW + d * D + 0] * r0
                  + sw[W_FORWW + d * D + 1] * r1
                  + sw[W_FORWW + d * D + 2] * r2
                  + sw[W_FORWW + d * D + 3] * r3;
        }

        float lg[VOCAB];
        float m2 = -3.4e38f;
        #pragma unroll
        for (int c = 0; c < VOCAB; c++) {
            float a = sw[W_PRJB + c];
            #pragma unroll
            for (int k = 0; k < D; k++)
                a += sw[W_PRJW + c * D + k] * h2[k];
            lg[c] = a;
            m2 = fmaxf(m2, a);
        }
        float zsum = 0.f;
        #pragma unroll
        for (int c = 0; c < VOCAB; c++) {
            lg[c] = __expf(lg[c] - m2);
            zsum += lg[c];
        }
        float zinv = 1.0f / zsum;
        #pragma unroll
        for (int c = 0; c < VOCAB; c++)
            sp[tid * VOCAB + c] = lg[c] * zinv;
    }
    __syncthreads();                              // B4: sp visible

    // ---- scatter: thread t owns output rows 4t .. 4t+3 ----
    float4* o = out4 + (size_t)t * 9;
    #pragma unroll
    for (int k = 0; k < 9; k++) {
        float4 f;
        f.x = sp[vals[(4 * k + 0) / 9] * VOCAB + (4 * k + 0) % 9];
        f.y = sp[vals[(4 * k + 1) / 9] * VOCAB + (4 * k + 1) % 9];
        f.z = sp[vals[(4 * k + 2) / 9] * VOCAB + (4 * k + 2) % 9];
        f.w = sp[vals[(4 * k + 3) / 9] * VOCAB + (4 * k + 3) % 9];
        o[k] = f;
    }

    // ---- replay-safe reset: last finishing block zeroes the globals ----
    if (tid == 0) {
        unsigned r = atomicAdd(&g_done, 1u);
        if (r == (unsigned)(NBLK - 1)) {
            #pragma unroll
            for (int q = 0; q < VOCAB; q++) g_cnt[q] = 0;
            g_arrive = 0u;
            __threadfence();
            g_done = 0u;
        }
    }
}

extern "C" void kernel_launch(void* const* d_in, const int* in_sizes, int n_in,
                              void* d_out, int out_size)
{
    const int*   x      = (const int*)d_in[0];
    const float* emb    = (const float*)d_in[1];
    const float* proj_w = (const float*)d_in[2];
    const float* proj_b = (const float*)d_in[3];
    const float* forw_w = (const float*)d_in[4];
    const float* forw_b = (const float*)d_in[5];
    const float* prj_w  = (const float*)d_in[6];
    const float* prj_b  = (const float*)d_in[7];
    float* out = (float*)d_out;

    bert_fused_kernel<<<NBLK, NTHR>>>(x, emb, proj_w, proj_b,
                                      forw_w, forw_b, prj_w, prj_b,
                                      (float4*)out);
    (void)in_sizes; (void)n_in; (void)out_size;
}

// round 13
// speedup vs baseline: 1.4173x; 1.0827x over previous
#include <cuda_runtime.h>

#define VOCAB 9
#define D     4
#define S     16384

#define NBLK  64
#define NTHR  64    // 2 warps; 64*64 = 4096 threads, 4 output rows each

// Packed shared weight layout (121 floats):
#define W_EMB   0
#define W_PROJW 36
#define W_PROJB 52
#define W_FORWW 56
#define W_FORWB 72
#define W_PRJW  76
#define W_PRJB  112
#define W_TOTAL 121

// Self-validating count words: word w holds counters 3w..3w+2 in 15-bit
// fields (bits 0,15,30; global max 16384 < 32767) and an arrive count at
// bits 45-51 (max NBLK=64 < 128). A word whose arrive field reads NBLK is
// final — no fence, no separate arrive counter. Zero at load; last
// finishing block resets for graph replays.
__device__ unsigned long long g_w[3];
__device__ unsigned           g_done;

// ---------------------------------------------------------------------------
// Distributed histogram, minimal serial chain.
//  probe p4[t] (valid both layouts) -> consensus detection -> gated upper/
//  payload loads (int64) with h0 math overlapping their latency -> REDUX ->
//  3 concurrent RED.ADD.64 (counters+arrive fused) -> 9 table threads poll
//  the 3 words, finish the 9x9 prob table -> scatter 4 rows/thread.
//  3 barriers total.
// ---------------------------------------------------------------------------
__global__ void __launch_bounds__(NTHR) bert_fused_kernel(
    const int* __restrict__ x32,
    const float* __restrict__ emb,
    const float* __restrict__ proj_w,
    const float* __restrict__ proj_b,
    const float* __restrict__ forw_w,
    const float* __restrict__ forw_b,
    const float* __restrict__ prj_w,
    const float* __restrict__ prj_b,
    float4* __restrict__ out4)
{
    __shared__ int   s_ok[2];
    __shared__ int   warp_cnt[2][VOCAB];
    __shared__ float sw[W_TOTAL + 7];
    __shared__ float h0s[VOCAB][D];
    __shared__ float sp[VOCAB * VOCAB];

    const int tid  = threadIdx.x;
    const int wid  = tid >> 5;
    const int lane = tid & 31;
    const int bid  = blockIdx.x;
    const int4* p4 = (const int4*)x32;
    const int t    = bid * NTHR + tid;  // probe index AND row-group id, <4096

    // ---- weight prefetch: 2 LDG per thread, issued first ----
    float wr0 = 0.f, wr1 = 0.f;
    {
        const float* srcs[2]; int n = 0;
        #pragma unroll
        for (int k = 0; k < 2; k++) {
            int q = tid + 64 * k;
            if (q < W_TOTAL) {
                const float* s;
                if      (q < W_PROJW) s = emb    + (q - W_EMB);
                else if (q < W_PROJB) s = proj_w + (q - W_PROJW);
                else if (q < W_FORWW) s = proj_b + (q - W_PROJB);
                else if (q < W_FORWB) s = forw_w + (q - W_FORWW);
                else if (q < W_PRJW)  s = forw_b + (q - W_FORWB);
                else if (q < W_PRJB)  s = prj_w  + (q - W_PRJW);
                else                  s = prj_b  + (q - W_PRJB);
                srcs[n++] = s;
            }
        }
        if (n > 0) wr0 = __ldg(srcs[0]);
        if (n > 1) wr1 = __ldg(srcs[1]);
    }

    // ---- probe load (1 int4/thread; in-bounds under both layouts) ----
    int4 pr = __ldg(p4 + t);

    // detection consensus: int64 LE <=> odd words 0, even words < 9
    bool okb = (pr.y == 0) && (pr.w == 0)
            && ((unsigned)pr.x < VOCAB) && ((unsigned)pr.z < VOCAB);
    unsigned wall = __all_sync(0xffffffffu, okb);
    if (lane == 0) s_ok[wid] = (int)(wall != 0);

    // count .x/.z (correct under both layouts); packed 9x7-bit counters
    // (per-thread field max 4 < 127; REDUX extracts fields before summing)
    unsigned long long acc = (1ULL << (7 * pr.x)) + (1ULL << (7 * pr.z));

    if (tid < W_TOTAL)      sw[tid]      = wr0;
    if (tid + 64 < W_TOTAL) sw[tid + 64] = wr1;
    __syncthreads();                              // B1: s_ok, sw

    const int is64 = s_ok[0] & s_ok[1];

    int  vals[4];
    int4 up, pl0, pl1;
    if (is64) {
        up  = __ldg(p4 + 4096 + t);               // tokens 8192+2t, 8193+2t
        pl0 = __ldg(p4 + 2 * t);                  // tokens 4t, 4t+1
        pl1 = __ldg(p4 + 2 * t + 1);              // tokens 4t+2, 4t+3
    } else {
        acc += (1ULL << (7 * pr.y)) + (1ULL << (7 * pr.w));
        vals[0] = pr.x; vals[1] = pr.y; vals[2] = pr.z; vals[3] = pr.w;
    }

    // ---- h0 math overlaps the gated-load latency (threads 0..35) ----
    if (tid < VOCAB * D) {
        int vv = tid / D, d = tid % D;
        float a = sw[W_PROJB + d];
        #pragma unroll
        for (int k = 0; k < D; k++)
            a += sw[W_EMB + vv * D + k] * sw[W_PROJW + d * D + k];
        h0s[vv][d] = a;
    }

    if (is64) {
        acc += (1ULL << (7 * up.x)) + (1ULL << (7 * up.z));
        vals[0] = pl0.x; vals[1] = pl0.z; vals[2] = pl1.x; vals[3] = pl1.z;
    }

    // ---- per-warp reduce: extract 7-bit fields, REDUX-sum ----
    #pragma unroll
    for (int q = 0; q < VOCAB; q++) {
        unsigned c  = (unsigned)((acc >> (7 * q)) & 127ULL);
        unsigned ws = __reduce_add_sync(0xffffffffu, c);
        if (lane == 0) warp_cnt[wid][q] = (int)ws;
    }
    __syncthreads();                              // B2: warp_cnt, h0s

    // ---- post: threads 0..2 each send one self-validating word.
    //      Single concurrent atomic round; no fence, no arrive atomic. ----
    if (tid < 3) {
        unsigned long long pack = 1ULL << 45;     // arrive += 1
        #pragma unroll
        for (int k = 0; k < 3; k++) {
            int q  = tid * 3 + k;
            int bc = warp_cnt[0][q] + warp_cnt[1][q];   // block total <= 256
            pack |= (unsigned long long)bc << (15 * k);
        }
        atomicAdd(&g_w[tid], pack);               // -> RED.ADD.64 (no return)
    }

    // ---- count-independent precompute (9 table threads) ----
    float eu[VOCAB];
    if (tid < VOCAB) {
        float hv0 = h0s[tid][0], hv1 = h0s[tid][1],
              hv2 = h0s[tid][2], hv3 = h0s[tid][3];
        float sc[VOCAB];
        float m = -3.4e38f;
        #pragma unroll
        for (int u = 0; u < VOCAB; u++) {
            float s = hv0 * h0s[u][0] + hv1 * h0s[u][1]
                    + hv2 * h0s[u][2] + hv3 * h0s[u][3];
            sc[u] = s;
            m = fmaxf(m, s);
        }
        #pragma unroll
        for (int u = 0; u < VOCAB; u++)
            eu[u] = __expf(sc[u] - m);

        // ---- poll the 3 words until every arrive field shows NBLK ----
        volatile unsigned long long* gw = g_w;
        unsigned long long w0, w1, w2;
        do {
            w0 = gw[0]; w1 = gw[1]; w2 = gw[2];
        } while (((w0 >> 45) & 0x7F) < (unsigned)NBLK ||
                 ((w1 >> 45) & 0x7F) < (unsigned)NBLK ||
                 ((w2 >> 45) & 0x7F) < (unsigned)NBLK);

        int cu[VOCAB];
        #pragma unroll
        for (int q = 0; q < VOCAB; q++) {
            unsigned long long w = (q < 3) ? w0 : (q < 6) ? w1 : w2;
            cu[q] = (int)((w >> (15 * (q % 3))) & 0x7FFFULL);
        }

        // grouped softmax-weighted sum: attn @ h (exact regrouping by token)
        float wsum = 0.f, a0 = 0.f, a1 = 0.f, a2 = 0.f, a3 = 0.f;
        #pragma unroll
        for (int u = 0; u < VOCAB; u++) {
            float e = eu[u] * (float)cu[u];
            wsum += e;
            a0 += e * h0s[u][0];
            a1 += e * h0s[u][1];
            a2 += e * h0s[u][2];
            a3 += e * h0s[u][3];
        }
        float inv = 1.0f / wsum;
        float r0 = fmaxf(0.f, a0 * inv), r1 = fmaxf(0.f, a1 * inv);
        float r2 = fmaxf(0.f, a2 * inv), r3 = fmaxf(0.f, a3 * inv);

        float h2[D];
        #pragma unroll
        for (int d = 0; d < D; d++) {
            h2[d] = sw[W_FORWB + d]
                  + sw[W_FORWW + d * D + 0] * r0
                  + sw[W_FORWW + d * D + 1] * r1
                  + sw[W_FORWW + d * D + 2] * r2
                  + sw[W_FORWW + d * D + 3] * r3;
        }

        float lg[VOCAB];
        float m2 = -3.4e38f;
        #pragma unroll
        for (int c = 0; c < VOCAB; c++) {
            float a = sw[W_PRJB + c];
            #pragma unroll
            for (int k = 0; k < D; k++)
                a += sw[W_PRJW + c * D + k] * h2[k];
            lg[c] = a;
            m2 = fmaxf(m2, a);
        }
        float zsum = 0.f;
        #pragma unroll
        for (int c = 0; c < VOCAB; c++) {
            lg[c] = __expf(lg[c] - m2);
            zsum += lg[c];
        }
        float zinv = 1.0f / zsum;
        #pragma unroll
        for (int c = 0; c < VOCAB; c++)
            sp[tid * VOCAB + c] = lg[c] * zinv;
    }
    __syncthreads();                              // B3: sp visible

    // ---- scatter: thread t owns output rows 4t .. 4t+3 ----
    float4* o = out4 + (size_t)t * 9;
    #pragma unroll
    for (int k = 0; k < 9; k++) {
        float4 f;
        f.x = sp[vals[(4 * k + 0) / 9] * VOCAB + (4 * k + 0) % 9];
        f.y = sp[vals[(4 * k + 1) / 9] * VOCAB + (4 * k + 1) % 9];
        f.z = sp[vals[(4 * k + 2) / 9] * VOCAB + (4 * k + 2) % 9];
        f.w = sp[vals[(4 * k + 3) / 9] * VOCAB + (4 * k + 3) % 9];
        o[k] = f;
    }

    // ---- replay-safe reset: last finishing block zeroes the words.
    //      g_done increments only after B3 + scatter, so every block's
    //      g_w reads completed before the reset can run. ----
    if (tid == 0) {
        unsigned r = atomicAdd(&g_done, 1u);
        if (r == (unsigned)(NBLK - 1)) {
            g_w[0] = 0ULL; g_w[1] = 0ULL; g_w[2] = 0ULL;
            __threadfence();
            g_done = 0u;
        }
    }
}

extern "C" void kernel_launch(void* const* d_in, const int* in_sizes, int n_in,
                              void* d_out, int out_size)
{
    const int*   x      = (const int*)d_in[0];
    const float* emb    = (const float*)d_in[1];
    const float* proj_w = (const float*)d_in[2];
    const float* proj_b = (const float*)d_in[3];
    const float* forw_w = (const float*)d_in[4];
    const float* forw_b = (const float*)d_in[5];
    const float* prj_w  = (const float*)d_in[6];
    const float* prj_b  = (const float*)d_in[7];
    float* out = (float*)d_out;

    bert_fused_kernel<<<NBLK, NTHR>>>(x, emb, proj_w, proj_b,
                                      forw_w, forw_b, prj_w, prj_b,
                                      (float4*)out);
    (void)in_sizes; (void)n_in; (void)out_size;
}